// round 1
// baseline (speedup 1.0000x reference)
#include <cuda_runtime.h>
#include <cuda_bf16.h>

// ---------------------------------------------------------------------------
// Problem constants
// ---------------------------------------------------------------------------
#define BATCH 2048
#define ENS   32
#define WIN   10
#define DX    14
#define DZ    14
#define RAWD  22

#define BE        (BATCH * ENS)          // 65536
#define PM_IN     (WIN * DX)             // 140
#define SM_IN     (WIN * RAWD)           // 220

// Output regions (concatenated flattened tuple)
#define O1_OFF 0                          // state_corrected [B,E,DX]
#define O1_LEN (BATCH * ENS * DX)         // 917504
#define O2_OFF (O1_OFF + O1_LEN)          // state_corrected mean [B,1,DX]
#define O2_LEN (BATCH * DX)
#define O3_OFF (O2_OFF + O2_LEN)          // state_m [B,1,DX]
#define O3_LEN (BATCH * DX)
#define O4_OFF (O3_OFF + O3_LEN)          // z [B,1,DZ]
#define O4_LEN (BATCH * DZ)
#define O5_OFF (O4_OFF + O4_LEN)          // ensemble_z [B,E,DZ]
#define O5_LEN (BATCH * ENS * DZ)

// ---------------------------------------------------------------------------
// Scratch (device globals: no allocation allowed)
// ---------------------------------------------------------------------------
__device__ float g_h1[BE * 256];     // 67 MB
__device__ float g_h2[BE * 512];     // 134 MB
__device__ float g_pred[BE * DX];    // state_pred
__device__ float g_sens[BATCH * DZ]; // sensor MLP on distinct rows

// ---------------------------------------------------------------------------
// Tiled SGEMM with bias + optional leaky-relu.  C[M,N] = act(A[M,K]@B[K,N]+b)
// BM=128 BN=128 BK=8 TM=8 TN=8, 256 threads. M%BM==0, N%BN==0 assumed.
// ---------------------------------------------------------------------------
template <int BM, int BN, int BK, int TM, int TN, bool LEAKY>
__global__ void __launch_bounds__(256)
sgemm_bias_act(const float* __restrict__ A, const float* __restrict__ B,
               const float* __restrict__ bias, float* __restrict__ C,
               int M, int N, int K)
{
    constexpr int NT = (BM / TM) * (BN / TN);   // 256
    __shared__ __align__(16) float As[BK][BM];
    __shared__ __align__(16) float Bs[BK][BN];

    const int tid  = threadIdx.x;
    const int crow = blockIdx.y * BM;
    const int ccol = blockIdx.x * BN;
    const int tcol = (tid % (BN / TN)) * TN;
    const int trow = (tid / (BN / TN)) * TM;

    float acc[TM][TN];
#pragma unroll
    for (int i = 0; i < TM; i++)
#pragma unroll
        for (int j = 0; j < TN; j++) acc[i][j] = 0.f;

    for (int k0 = 0; k0 < K; k0 += BK) {
        // load A tile (BM x BK)
#pragma unroll
        for (int i = 0; i < BM * BK; i += NT) {
            int idx = i + tid;
            int m = idx / BK, kk = idx % BK;
            As[kk][m] = (k0 + kk < K) ? A[(size_t)(crow + m) * K + k0 + kk] : 0.f;
        }
        // load B tile (BK x BN)
#pragma unroll
        for (int i = 0; i < BK * BN; i += NT) {
            int idx = i + tid;
            int kk = idx / BN, n = idx % BN;
            Bs[kk][n] = (k0 + kk < K) ? B[(size_t)(k0 + kk) * N + ccol + n] : 0.f;
        }
        __syncthreads();

#pragma unroll
        for (int kk = 0; kk < BK; kk++) {
            float ra[TM], rb[TN];
#pragma unroll
            for (int i = 0; i < TM; i += 4) {
                float4 v = *(const float4*)&As[kk][trow + i];
                ra[i] = v.x; ra[i + 1] = v.y; ra[i + 2] = v.z; ra[i + 3] = v.w;
            }
#pragma unroll
            for (int j = 0; j < TN; j += 4) {
                float4 v = *(const float4*)&Bs[kk][tcol + j];
                rb[j] = v.x; rb[j + 1] = v.y; rb[j + 2] = v.z; rb[j + 3] = v.w;
            }
#pragma unroll
            for (int i = 0; i < TM; i++)
#pragma unroll
                for (int j = 0; j < TN; j++) acc[i][j] += ra[i] * rb[j];
        }
        __syncthreads();
    }

#pragma unroll
    for (int i = 0; i < TM; i++) {
#pragma unroll
        for (int j = 0; j < TN; j++) {
            float v = acc[i][j] + bias[ccol + tcol + j];
            if (LEAKY) v = (v >= 0.f) ? v : 0.01f * v;
            C[(size_t)(crow + trow + i) * N + ccol + tcol + j] = v;
        }
    }
}

// ---------------------------------------------------------------------------
// PM stage 3: pred[M,14] = h2[M,512] @ W[512,14] + b.  One warp per row.
// ---------------------------------------------------------------------------
__global__ void __launch_bounds__(256)
pm_out_kernel(const float* __restrict__ h2, const float* __restrict__ W,
              const float* __restrict__ bias, float* __restrict__ pred)
{
    __shared__ float Ws[512 * DX];
    __shared__ float bs[DX];
    const int tid = threadIdx.x;
    for (int i = tid; i < 512 * DX; i += 256) Ws[i] = W[i];
    if (tid < DX) bs[tid] = bias[tid];
    __syncthreads();

    const int warp = tid >> 5, lane = tid & 31;
    const int row = blockIdx.x * 8 + warp;
    const float* hrow = h2 + (size_t)row * 512;

    float h[16];
#pragma unroll
    for (int i = 0; i < 16; i++) h[i] = hrow[lane + 32 * i];

    float out[DX];
#pragma unroll
    for (int c = 0; c < DX; c++) {
        float acc = 0.f;
#pragma unroll
        for (int i = 0; i < 16; i++) acc += h[i] * Ws[(lane + 32 * i) * DX + c];
#pragma unroll
        for (int off = 16; off > 0; off >>= 1) acc += __shfl_xor_sync(0xFFFFFFFFu, acc, off);
        out[c] = acc;
    }
    if (lane == 0) {
#pragma unroll
        for (int c = 0; c < DX; c++) pred[(size_t)row * DX + c] = out[c] + bs[c];
    }
}

// ---------------------------------------------------------------------------
// Sensor MLP on the 2048 DISTINCT raw_obs rows: 220->256->256->64->14.
// 8 rows per block, 256 threads (thread = output column).
// ---------------------------------------------------------------------------
__global__ void __launch_bounds__(256)
sensor_kernel(const float* __restrict__ raw,
              const float* __restrict__ w2, const float* __restrict__ b2,
              const float* __restrict__ w3, const float* __restrict__ b3,
              const float* __restrict__ w5, const float* __restrict__ b5,
              const float* __restrict__ w6, const float* __restrict__ b6,
              float* __restrict__ sens)
{
    __shared__ float s[8][SM_IN];
    __shared__ float h1[8][256];
    __shared__ float h2[8][256];
    __shared__ float h3[8][64];

    const int tid = threadIdx.x;
    const int row0 = blockIdx.x * 8;

    for (int i = tid; i < 8 * SM_IN; i += 256) {
        int r = i / SM_IN, k = i % SM_IN;
        s[r][k] = raw[(size_t)(row0 + r) * SM_IN + k];
    }
    __syncthreads();

    {   // layer 1: 220 -> 256, leaky
        float acc[8];
#pragma unroll
        for (int r = 0; r < 8; r++) acc[r] = b2[tid];
        for (int k = 0; k < SM_IN; k++) {
            float w = w2[k * 256 + tid];
#pragma unroll
            for (int r = 0; r < 8; r++) acc[r] += s[r][k] * w;
        }
#pragma unroll
        for (int r = 0; r < 8; r++) {
            float v = acc[r];
            h1[r][tid] = (v >= 0.f) ? v : 0.01f * v;
        }
    }
    __syncthreads();

    {   // layer 2: 256 -> 256, leaky
        float acc[8];
#pragma unroll
        for (int r = 0; r < 8; r++) acc[r] = b3[tid];
        for (int k = 0; k < 256; k++) {
            float w = w3[k * 256 + tid];
#pragma unroll
            for (int r = 0; r < 8; r++) acc[r] += h1[r][k] * w;
        }
#pragma unroll
        for (int r = 0; r < 8; r++) {
            float v = acc[r];
            h2[r][tid] = (v >= 0.f) ? v : 0.01f * v;
        }
    }
    __syncthreads();

    if (tid < 64) {  // layer 3: 256 -> 64, leaky
        float acc[8];
#pragma unroll
        for (int r = 0; r < 8; r++) acc[r] = b5[tid];
        for (int k = 0; k < 256; k++) {
            float w = w5[k * 64 + tid];
#pragma unroll
            for (int r = 0; r < 8; r++) acc[r] += h2[r][k] * w;
        }
#pragma unroll
        for (int r = 0; r < 8; r++) {
            float v = acc[r];
            h3[r][tid] = (v >= 0.f) ? v : 0.01f * v;
        }
    }
    __syncthreads();

    if (tid < DZ) {  // layer 4: 64 -> 14, linear
        float acc[8];
#pragma unroll
        for (int r = 0; r < 8; r++) acc[r] = b6[tid];
        for (int k = 0; k < 64; k++) {
            float w = w6[k * DZ + tid];
#pragma unroll
            for (int r = 0; r < 8; r++) acc[r] += h3[r][k] * w;
        }
#pragma unroll
        for (int r = 0; r < 8; r++) sens[(size_t)(row0 + r) * DZ + tid] = acc[r];
    }
}

// ---------------------------------------------------------------------------
// EnKF correction per batch element. One CTA (256 threads) per b.
// ---------------------------------------------------------------------------
__global__ void __launch_bounds__(256)
enkf_kernel(const float* __restrict__ pred_g, const float* __restrict__ sens,
            const float* __restrict__ on_w1, const float* __restrict__ on_b1,
            const float* __restrict__ on_w2, const float* __restrict__ on_b2,
            float* __restrict__ out1, float* __restrict__ out2,
            float* __restrict__ out3, float* __restrict__ out4,
            float* __restrict__ out5)
{
    const int b = blockIdx.x;
    const int tid = threadIdx.x;

    __shared__ float pred[ENS][DX], ez[ENS][DZ], Am[ENS][DX], corr[ENS][DX];
    __shared__ float sm[DX], zm[DZ], rdiag[DZ], hid[32];
    __shared__ float Mm[DX][DX];
    __shared__ float Km[DX][DZ];
    __shared__ float aug[DX][2 * DX];
    __shared__ float fac[DX];

    // load state_pred rows and ensemble_z (gather with the tile/reshape aliasing)
    for (int i = tid; i < ENS * DX; i += 256) {
        pred[i / DX][i % DX] = pred_g[(size_t)b * ENS * DX + i];
    }
    for (int i = tid; i < ENS * DZ; i += 256) {
        int e = i / DZ, j = i % DZ;
        int src = (b * ENS + e) % BATCH;
        float v = sens[src * DZ + j];
        ez[e][j] = v;
        out5[(size_t)(b * ENS + e) * DZ + j] = v;
    }
    __syncthreads();

    if (tid < DX) {
        float s1 = 0.f, s2 = 0.f;
        for (int e = 0; e < ENS; e++) { s1 += pred[e][tid]; s2 += ez[e][tid]; }
        float m1 = s1 * (1.f / ENS), m2 = s2 * (1.f / ENS);
        sm[tid] = m1; zm[tid] = m2;
        out3[b * DX + tid] = m1;
        out4[b * DZ + tid] = m2;
    }
    __syncthreads();

    // observation noise R = diag( (relu(z@W1+b1)@W2+b2 + 1e-3)^2 + 0.038729833 )
    if (tid < 32) {
        float a = on_b1[tid];
        for (int i = 0; i < DZ; i++) a += zm[i] * on_w1[i * 32 + tid];
        hid[tid] = (a > 0.f) ? a : 0.f;
    }
    __syncthreads();
    if (tid < DZ) {
        float a = on_b2[tid];
        for (int j = 0; j < 32; j++) a += hid[j] * on_w2[j * DZ + tid];
        a += 0.001f;
        rdiag[tid] = a * a + 0.038729833f;
    }
    // anomalies
    for (int i = tid; i < ENS * DX; i += 256) {
        int e = i / DX, j = i % DX;
        Am[e][j] = pred[e][j] - sm[j];
    }
    __syncthreads();

    // S/(E-1) and augmented [innovation | I]
    if (tid < DX * DX) {
        int i = tid / DX, j = tid % DX;
        float s = 0.f;
        for (int e = 0; e < ENS; e++) s += Am[e][i] * Am[e][j];
        float m = s * (1.f / (ENS - 1));
        Mm[i][j] = m;
        aug[i][j] = m + ((i == j) ? rdiag[i] : 0.f);
        aug[i][DX + j] = (i == j) ? 1.f : 0.f;
    }
    __syncthreads();

    // Gauss-Jordan (SPD -> no pivoting needed)
    for (int p = 0; p < DX; p++) {
        float pv = aug[p][p];            // all threads read before anyone writes
        __syncthreads();
        if (tid < 2 * DX) aug[p][tid] *= (1.f / pv);
        if (tid < DX) fac[tid] = (tid == p) ? 0.f : aug[tid][p];
        __syncthreads();
        for (int t = tid; t < DX * 2 * DX; t += 256) {
            int r = t / (2 * DX), c = t % (2 * DX);
            if (r != p) aug[r][c] -= fac[r] * aug[p][c];
        }
        __syncthreads();
    }

    // K = (S/(E-1)) @ inv(innovation)
    if (tid < DX * DX) {
        int i = tid / DX, j = tid % DX;
        float s = 0.f;
        for (int k = 0; k < DX; k++) s += Mm[i][k] * aug[k][DX + j];
        Km[i][j] = s;
    }
    __syncthreads();

    // gain + corrected state
    for (int t = tid; t < ENS * DX; t += 256) {
        int e = t / DX, i = t % DX;
        float s = pred[e][i];
        for (int j = 0; j < DZ; j++) s += Km[i][j] * (ez[e][j] - pred[e][j]);
        corr[e][i] = s;
        out1[(size_t)(b * ENS + e) * DX + i] = s;
    }
    __syncthreads();
    if (tid < DX) {
        float s = 0.f;
        for (int e = 0; e < ENS; e++) s += corr[e][tid];
        out2[b * DX + tid] = s * (1.f / ENS);
    }
}

// ---------------------------------------------------------------------------
// Launcher
// ---------------------------------------------------------------------------
extern "C" void kernel_launch(void* const* d_in, const int* in_sizes, int n_in,
                              void* d_out, int out_size)
{
    const float* raw      = (const float*)d_in[0];
    const float* sp       = (const float*)d_in[1];
    const float* pm_w1    = (const float*)d_in[2];
    const float* pm_b1    = (const float*)d_in[3];
    const float* pm_w3    = (const float*)d_in[4];
    const float* pm_b3    = (const float*)d_in[5];
    const float* pm_wm2   = (const float*)d_in[6];
    const float* pm_bm2   = (const float*)d_in[7];
    const float* sm_w2    = (const float*)d_in[8];
    const float* sm_b2    = (const float*)d_in[9];
    const float* sm_w3    = (const float*)d_in[10];
    const float* sm_b3    = (const float*)d_in[11];
    const float* sm_w5    = (const float*)d_in[12];
    const float* sm_b5    = (const float*)d_in[13];
    const float* sm_w6    = (const float*)d_in[14];
    const float* sm_b6    = (const float*)d_in[15];
    const float* on_w1    = (const float*)d_in[16];
    const float* on_b1    = (const float*)d_in[17];
    const float* on_w2    = (const float*)d_in[18];
    const float* on_b2    = (const float*)d_in[19];

    float* out = (float*)d_out;
    float* out1 = out + O1_OFF;
    float* out2 = out + O2_OFF;
    float* out3 = out + O3_OFF;
    float* out4 = out + O4_OFF;
    float* out5 = out + O5_OFF;

    float *h1p, *h2p, *predp, *sensp;
    cudaGetSymbolAddress((void**)&h1p,   g_h1);
    cudaGetSymbolAddress((void**)&h2p,   g_h2);
    cudaGetSymbolAddress((void**)&predp, g_pred);
    cudaGetSymbolAddress((void**)&sensp, g_sens);

    // Process model: 140 -> 256 -> 512 -> 14
    sgemm_bias_act<128, 128, 8, 8, 8, true>
        <<<dim3(256 / 128, BE / 128), 256>>>(sp, pm_w1, pm_b1, h1p, BE, 256, PM_IN);
    sgemm_bias_act<128, 128, 8, 8, 8, true>
        <<<dim3(512 / 128, BE / 128), 256>>>(h1p, pm_w3, pm_b3, h2p, BE, 512, 256);
    pm_out_kernel<<<BE / 8, 256>>>(h2p, pm_wm2, pm_bm2, predp);

    // Sensor model on distinct rows only (tile aliasing exploited)
    sensor_kernel<<<BATCH / 8, 256>>>(raw, sm_w2, sm_b2, sm_w3, sm_b3,
                                      sm_w5, sm_b5, sm_w6, sm_b6, sensp);

    // EnKF correction + all outputs
    enkf_kernel<<<BATCH, 256>>>(predp, sensp, on_w1, on_b1, on_w2, on_b2,
                                out1, out2, out3, out4, out5);
}